// round 9
// baseline (speedup 1.0000x reference)
#include <cuda_runtime.h>
#include <cuda_bf16.h>
#include <cstddef>

// ---------------- problem constants ----------------
#define NN    2000     // nodes
#define BB    64       // batch
#define EE    10       // embed dim
#define HH    64       // hidden
#define DIN   2        // input dim
#define CIN   66       // Din + H
#define CG    132      // K * CIN (K=2 cheb)
#define OG    192      // gate out (3H)
#define OU    64       // update/space out (H)
#define COLSX 4224     // BB*CIN
#define COLS  8448     // 2*COLSX (X cols then Y cols)
#define BNH   8192000  // BB*NN*HH

// ---------------- device scratch (static module memory; no runtime alloc) ----------------
__device__ float d_supports[NN * NN];
__device__ float d_XY[(size_t)NN * COLS];
__device__ float d_XG[(size_t)NN * BB * CG];
__device__ float d_YG[(size_t)NN * BB * CG];
__device__ float d_Wg[(size_t)NN * CG * OG];
__device__ float d_Wu[(size_t)NN * CG * OU];
__device__ float d_Ws[(size_t)NN * CG * OU];
__device__ float d_bg[NN * OG];
__device__ float d_bu[NN * OU];
__device__ float d_bs[NN * OU];

// Host-side copies of the REAL device addresses of the weight/bias scratch.
// CRITICAL: passing `d_Wg` etc. directly as a kernel argument from host code
// passes the HOST shadow symbol address (silently "works" via ATS on this
// coherent Grace host, writing host memory) — the device arrays stay zero.
// These are resolved once via cudaGetSymbolAddress in the pre-main warmup.
static float* g_Wg = nullptr;
static float* g_Wu = nullptr;
static float* g_Ws = nullptr;
static float* g_bg = nullptr;
static float* g_bu = nullptr;
static float* g_bs = nullptr;

// ---------------- kernel 1: supports = softmax(relu(NE NE^T), axis=1) ----------------
__global__ __launch_bounds__(256) void supports_kernel(const float* __restrict__ ne) {
    int n = blockIdx.x;
    float nrow[EE];
#pragma unroll
    for (int d = 0; d < EE; d++) nrow[d] = ne[n * EE + d];

    __shared__ float red[256];
    int t = threadIdx.x;

    float lmax = 0.f;
    for (int m = t; m < NN; m += 256) {
        float s = 0.f;
#pragma unroll
        for (int d = 0; d < EE; d++) s += nrow[d] * __ldg(&ne[m * EE + d]);
        s = fmaxf(s, 0.f);
        d_supports[(size_t)n * NN + m] = s;
        lmax = fmaxf(lmax, s);
    }
    red[t] = lmax; __syncthreads();
    for (int o = 128; o > 0; o >>= 1) { if (t < o) red[t] = fmaxf(red[t], red[t + o]); __syncthreads(); }
    float mx = red[0];
    __syncthreads();

    float lsum = 0.f;
    for (int m = t; m < NN; m += 256) {
        float v = expf(d_supports[(size_t)n * NN + m] - mx);
        d_supports[(size_t)n * NN + m] = v;
        lsum += v;
    }
    red[t] = lsum; __syncthreads();
    for (int o = 128; o > 0; o >>= 1) { if (t < o) red[t] += red[t + o]; __syncthreads(); }
    float inv = 1.f / red[0];
    for (int m = t; m < NN; m += 256) d_supports[(size_t)n * NN + m] *= inv;
}

// ---------------- kernel 2: per-node weights / biases ----------------
// W[(n*J + j)*O + o] = sum_d ne[n,d] * pool[(d*J + j)*O + o]
__global__ __launch_bounds__(256) void mat_weights(const float* __restrict__ ne,
                                                   const float* __restrict__ pool,
                                                   float* __restrict__ W, int J, int O) {
    long total = (long)NN * J * O;
    long stride = (long)gridDim.x * blockDim.x;
    for (long idx = (long)blockIdx.x * blockDim.x + threadIdx.x; idx < total; idx += stride) {
        int o  = (int)(idx % O);
        long t2 = idx / O;
        int j  = (int)(t2 % J);
        int n  = (int)(t2 / J);
        float s = 0.f;
#pragma unroll
        for (int d = 0; d < EE; d++)
            s += ne[n * EE + d] * __ldg(&pool[((size_t)d * J + j) * O + o]);
        W[idx] = s;
    }
}

// ---------------- kernel 3: pack inputs node-major ----------------
__global__ __launch_bounds__(256) void pack_kernel(const float* __restrict__ x,
                                                   const float* __restrict__ y,
                                                   const float* __restrict__ state,
                                                   const float* __restrict__ lstate) {
    int total = NN * BB * CIN;
    int stride = gridDim.x * blockDim.x;
    for (int idx = blockIdx.x * blockDim.x + threadIdx.x; idx < total; idx += stride) {
        int i = idx % CIN;
        int t2 = idx / CIN;
        int b = t2 % BB;
        int n = t2 / BB;
        float vx, vy;
        if (i < DIN) {
            vx = x[((size_t)b * NN + n) * DIN + i];
            vy = y[((size_t)b * NN + n) * DIN + i];
        } else {
            vx = state[((size_t)b * NN + n) * HH + (i - DIN)];
            vy = lstate[((size_t)b * NN + n) * HH + (i - DIN)];
        }
        d_XG[((size_t)n * BB + b) * CG + i] = vx;
        d_YG[((size_t)n * BB + b) * CG + i] = vy;
        d_XY[(size_t)n * COLS + b * CIN + i] = vx;
        d_XY[(size_t)n * COLS + COLSX + b * CIN + i] = vy;
    }
}

// ---------------- kernel 4: SGEMM (single-buffered, BK=8) ----------------
#define BM 128
#define BN 128
__global__ __launch_bounds__(256) void sgemm2() {
    __shared__ float As[8][BM + 4];
    __shared__ float Bs[8][BN];

    int row0 = blockIdx.y * BM;
    int col0 = blockIdx.x * BN;
    int tid = threadIdx.x;
    int ty = tid >> 4, tx = tid & 15;

    int ar = tid >> 1;
    int ak = (tid & 1) * 4;
    int br = tid >> 5;
    int bc = (tid & 31) * 4;

    float acc[8][8];
#pragma unroll
    for (int i = 0; i < 8; i++)
#pragma unroll
        for (int j = 0; j < 8; j++) acc[i][j] = 0.f;

    for (int k0 = 0; k0 < NN; k0 += 8) {
        int gr = row0 + ar;
        float4 av = make_float4(0.f, 0.f, 0.f, 0.f);
        if (gr < NN) av = *(const float4*)&d_supports[(size_t)gr * NN + k0 + ak];
        float4 bv = *(const float4*)&d_XY[(size_t)(k0 + br) * COLS + col0 + bc];

        __syncthreads();
        As[ak + 0][ar] = av.x; As[ak + 1][ar] = av.y;
        As[ak + 2][ar] = av.z; As[ak + 3][ar] = av.w;
        *(float4*)&Bs[br][bc] = bv;
        __syncthreads();

#pragma unroll
        for (int kk = 0; kk < 8; kk++) {
            float4 a0 = *(const float4*)&As[kk][ty * 8];
            float4 a1 = *(const float4*)&As[kk][ty * 8 + 4];
            float4 b0 = *(const float4*)&Bs[kk][tx * 8];
            float4 b1 = *(const float4*)&Bs[kk][tx * 8 + 4];
            acc[0][0] = fmaf(a0.x, b0.x, acc[0][0]); acc[0][1] = fmaf(a0.x, b0.y, acc[0][1]);
            acc[0][2] = fmaf(a0.x, b0.z, acc[0][2]); acc[0][3] = fmaf(a0.x, b0.w, acc[0][3]);
            acc[0][4] = fmaf(a0.x, b1.x, acc[0][4]); acc[0][5] = fmaf(a0.x, b1.y, acc[0][5]);
            acc[0][6] = fmaf(a0.x, b1.z, acc[0][6]); acc[0][7] = fmaf(a0.x, b1.w, acc[0][7]);
            acc[1][0] = fmaf(a0.y, b0.x, acc[1][0]); acc[1][1] = fmaf(a0.y, b0.y, acc[1][1]);
            acc[1][2] = fmaf(a0.y, b0.z, acc[1][2]); acc[1][3] = fmaf(a0.y, b0.w, acc[1][3]);
            acc[1][4] = fmaf(a0.y, b1.x, acc[1][4]); acc[1][5] = fmaf(a0.y, b1.y, acc[1][5]);
            acc[1][6] = fmaf(a0.y, b1.z, acc[1][6]); acc[1][7] = fmaf(a0.y, b1.w, acc[1][7]);
            acc[2][0] = fmaf(a0.z, b0.x, acc[2][0]); acc[2][1] = fmaf(a0.z, b0.y, acc[2][1]);
            acc[2][2] = fmaf(a0.z, b0.z, acc[2][2]); acc[2][3] = fmaf(a0.z, b0.w, acc[2][3]);
            acc[2][4] = fmaf(a0.z, b1.x, acc[2][4]); acc[2][5] = fmaf(a0.z, b1.y, acc[2][5]);
            acc[2][6] = fmaf(a0.z, b1.z, acc[2][6]); acc[2][7] = fmaf(a0.z, b1.w, acc[2][7]);
            acc[3][0] = fmaf(a0.w, b0.x, acc[3][0]); acc[3][1] = fmaf(a0.w, b0.y, acc[3][1]);
            acc[3][2] = fmaf(a0.w, b0.z, acc[3][2]); acc[3][3] = fmaf(a0.w, b0.w, acc[3][3]);
            acc[3][4] = fmaf(a0.w, b1.x, acc[3][4]); acc[3][5] = fmaf(a0.w, b1.y, acc[3][5]);
            acc[3][6] = fmaf(a0.w, b1.z, acc[3][6]); acc[3][7] = fmaf(a0.w, b1.w, acc[3][7]);
            acc[4][0] = fmaf(a1.x, b0.x, acc[4][0]); acc[4][1] = fmaf(a1.x, b0.y, acc[4][1]);
            acc[4][2] = fmaf(a1.x, b0.z, acc[4][2]); acc[4][3] = fmaf(a1.x, b0.w, acc[4][3]);
            acc[4][4] = fmaf(a1.x, b1.x, acc[4][4]); acc[4][5] = fmaf(a1.x, b1.y, acc[4][5]);
            acc[4][6] = fmaf(a1.x, b1.z, acc[4][6]); acc[4][7] = fmaf(a1.x, b1.w, acc[4][7]);
            acc[5][0] = fmaf(a1.y, b0.x, acc[5][0]); acc[5][1] = fmaf(a1.y, b0.y, acc[5][1]);
            acc[5][2] = fmaf(a1.y, b0.z, acc[5][2]); acc[5][3] = fmaf(a1.y, b0.w, acc[5][3]);
            acc[5][4] = fmaf(a1.y, b1.x, acc[5][4]); acc[5][5] = fmaf(a1.y, b1.y, acc[5][5]);
            acc[5][6] = fmaf(a1.y, b1.z, acc[5][6]); acc[5][7] = fmaf(a1.y, b1.w, acc[5][7]);
            acc[6][0] = fmaf(a1.z, b0.x, acc[6][0]); acc[6][1] = fmaf(a1.z, b0.y, acc[6][1]);
            acc[6][2] = fmaf(a1.z, b0.z, acc[6][2]); acc[6][3] = fmaf(a1.z, b0.w, acc[6][3]);
            acc[6][4] = fmaf(a1.z, b1.x, acc[6][4]); acc[6][5] = fmaf(a1.z, b1.y, acc[6][5]);
            acc[6][6] = fmaf(a1.z, b1.z, acc[6][6]); acc[6][7] = fmaf(a1.z, b1.w, acc[6][7]);
            acc[7][0] = fmaf(a1.w, b0.x, acc[7][0]); acc[7][1] = fmaf(a1.w, b0.y, acc[7][1]);
            acc[7][2] = fmaf(a1.w, b0.z, acc[7][2]); acc[7][3] = fmaf(a1.w, b0.w, acc[7][3]);
            acc[7][4] = fmaf(a1.w, b1.x, acc[7][4]); acc[7][5] = fmaf(a1.w, b1.y, acc[7][5]);
            acc[7][6] = fmaf(a1.w, b1.z, acc[7][6]); acc[7][7] = fmaf(a1.w, b1.w, acc[7][7]);
        }
    }

#pragma unroll
    for (int i = 0; i < 8; i++) {
        int n = row0 + ty * 8 + i;
        if (n >= NN) continue;
#pragma unroll
        for (int j = 0; j < 8; j++) {
            int c = col0 + tx * 8 + j;
            float v = acc[i][j];
            float* dst;
            int cc = c;
            if (cc < COLSX) { dst = d_XG; }
            else            { dst = d_YG; cc -= COLSX; }
            int b = cc / CIN, ii = cc % CIN;
            dst[((size_t)n * BB + b) * CG + CIN + ii] = v;
        }
    }
}

// ---------------- kernel 5: per-node matmuls + LSTM ----------------
__device__ __forceinline__ float sigmoidf_(float v) { return 1.f / (1.f + expf(-v)); }

__global__ __launch_bounds__(1024) void final2(const float* __restrict__ cell,
                                               float* __restrict__ out, int out_elems) {
    extern __shared__ float smem[];
    float* sx = smem;
    float* sy = smem + BB * CG;

    int n = blockIdx.x;
    int t = threadIdx.x;

    const float4* gx = (const float4*)&d_XG[(size_t)n * BB * CG];
    const float4* gy = (const float4*)&d_YG[(size_t)n * BB * CG];
    for (int i = t; i < BB * CG / 4; i += 1024) {
        ((float4*)sx)[i] = gx[i];
        ((float4*)sy)[i] = gy[i];
    }
    __syncthreads();

    int ou = t & 63;
    int b0 = (t >> 6) * 4;

    const float* wg = d_Wg + (size_t)n * CG * OG;
    const float* wu = d_Wu + (size_t)n * CG * OU;
    const float* ws = d_Ws + (size_t)n * CG * OU;

    float af[4] = {0.f, 0.f, 0.f, 0.f};
    float ai[4] = {0.f, 0.f, 0.f, 0.f};
    float ao[4] = {0.f, 0.f, 0.f, 0.f};
    float ag[4] = {0.f, 0.f, 0.f, 0.f};
    float as_[4] = {0.f, 0.f, 0.f, 0.f};

    for (int j = 0; j < CG; j++) {
        float wf  = __ldg(&wg[j * OG + ou]);
        float wi  = __ldg(&wg[j * OG + 64 + ou]);
        float wo  = __ldg(&wg[j * OG + 128 + ou]);
        float wuv = __ldg(&wu[j * OU + ou]);
        float wsv = __ldg(&ws[j * OU + ou]);
#pragma unroll
        for (int r = 0; r < 4; r++) {
            float xv = sx[(b0 + r) * CG + j];
            float yv = sy[(b0 + r) * CG + j];
            af[r]  = fmaf(wf,  xv, af[r]);
            ai[r]  = fmaf(wi,  xv, ai[r]);
            ao[r]  = fmaf(wo,  xv, ao[r]);
            ag[r]  = fmaf(wuv, xv, ag[r]);
            as_[r] = fmaf(wsv, yv, as_[r]);
        }
    }

    float bf = d_bg[n * OG + ou];
    float bi = d_bg[n * OG + 64 + ou];
    float bo = d_bg[n * OG + 128 + ou];
    float bu = d_bu[n * OU + ou];
    float bs = d_bs[n * OU + ou];

#pragma unroll
    for (int r = 0; r < 4; r++) {
        int b = b0 + r;
        float f  = sigmoidf_(af[r] + bf);
        float i2 = sigmoidf_(ai[r] + bi);
        float o2 = sigmoidf_(ao[r] + bo);
        float g  = tanhf(ag[r] + bu);
        float s  = sigmoidf_(as_[r] + bs);
        size_t base = ((size_t)b * NN + n) * HH + ou;
        float c = fmaf(f, cell[base], i2 * g);
        out[base] = o2 * tanhf(c);                                        // h
        if (BNH + base < (size_t)out_elems)     out[BNH + base] = c;      // c
        if (2 * BNH + base < (size_t)out_elems) out[2 * BNH + base] = s;  // new_last_state
    }
}

// ---------------- dummy kernel: force a generous local-memory pool ----------------
__global__ __launch_bounds__(256) void lmem_warm_kernel(float* sink) {
    volatile float buf[512];
    for (int i = 0; i < 512; i++) buf[i] = (float)(i ^ (int)threadIdx.x);
    float s = 0.f;
    for (int i = 0; i < 512; i++) s += buf[i];
    if (s < -1e30f) sink[0] = s;
}

// ---------------- full launch sequence (shared by warmup + real) ----------------
// NOTE: weight/bias destinations are passed as REAL device addresses (resolved
// via cudaGetSymbolAddress), never as raw __device__ symbol names from host.
static void launch_all(const float* x, const float* y, const float* state,
                       const float* cell, const float* lstate, const float* ne,
                       const float* gate_w, const float* gate_b,
                       const float* update_w, const float* update_b,
                       const float* space_w, const float* space_b,
                       float* out, int out_elems) {
    supports_kernel<<<NN, 256>>>(ne);
    long totG = (long)NN * CG * OG;
    long totU = (long)NN * CG * OU;
    mat_weights<<<(int)((totG + 255) / 256), 256>>>(ne, gate_w,   g_Wg, CG, OG);
    mat_weights<<<(int)((totU + 255) / 256), 256>>>(ne, update_w, g_Wu, CG, OU);
    mat_weights<<<(int)((totU + 255) / 256), 256>>>(ne, space_w,  g_Ws, CG, OU);
    mat_weights<<<(NN * OG + 255) / 256, 256>>>(ne, gate_b,   g_bg, 1, OG);
    mat_weights<<<(NN * OU + 255) / 256, 256>>>(ne, update_b, g_bu, 1, OU);
    mat_weights<<<(NN * OU + 255) / 256, 256>>>(ne, space_b,  g_bs, 1, OU);
    pack_kernel<<<(NN * BB * CIN + 255) / 256, 256>>>(x, y, state, lstate);
    sgemm2<<<dim3(COLS / BN, (NN + BM - 1) / BM), 256>>>();
    final2<<<NN, 1024, 2 * BB * CG * (int)sizeof(float)>>>(cell, out, out_elems);
}

// ---------------- static-init warmup (pre-main, pre-checkpoint) ----------------
namespace {
struct Warmup {
    Warmup() {
        cudaFuncSetAttribute(final2, cudaFuncAttributeMaxDynamicSharedMemorySize,
                             2 * BB * CG * (int)sizeof(float));
        // Resolve REAL device addresses for all __device__ scratch we pass as args.
        cudaGetSymbolAddress((void**)&g_Wg, d_Wg);
        cudaGetSymbolAddress((void**)&g_Wu, d_Wu);
        cudaGetSymbolAddress((void**)&g_Ws, d_Ws);
        cudaGetSymbolAddress((void**)&g_bg, d_bg);
        cudaGetSymbolAddress((void**)&g_bu, d_bu);
        cudaGetSymbolAddress((void**)&g_bs, d_bs);
        float* scratchA = nullptr;   // d_XY: 16.9M floats
        float* scratchB = nullptr;   // d_Wg: 50.7M floats (as warmup out buffer)
        cudaGetSymbolAddress((void**)&scratchA, d_XY);
        cudaGetSymbolAddress((void**)&scratchB, d_Wg);
        if (scratchA && scratchB && g_Wg) {
            lmem_warm_kernel<<<592, 256>>>(scratchA);
            launch_all(scratchA, scratchA, scratchA, scratchA, scratchA, scratchA,
                       scratchA, scratchA, scratchA, scratchA, scratchA, scratchA,
                       scratchB, 3 * BNH);
        }
        cudaDeviceSynchronize();
        cudaGetLastError();
    }
};
Warmup g_warmup;
}  // namespace

// ---------------- launch (inputs in setup_inputs dict order, per R7 size probe) ----
extern "C" void kernel_launch(void* const* d_in, const int* in_sizes, int n_in,
                              void* d_out, int out_size) {
    const float* x        = (const float*)d_in[0];
    const float* y        = (const float*)d_in[1];
    const float* state    = (const float*)d_in[2];
    const float* cell     = (const float*)d_in[3];
    const float* lstate   = (const float*)d_in[4];
    const float* ne       = (const float*)d_in[5];
    const float* gate_w   = (const float*)d_in[6];
    const float* gate_b   = (const float*)d_in[7];
    const float* update_w = (const float*)d_in[8];
    const float* update_b = (const float*)d_in[9];
    const float* space_w  = (const float*)d_in[10];
    const float* space_b  = (const float*)d_in[11];

    launch_all(x, y, state, cell, lstate, ne,
               gate_w, gate_b, update_w, update_b, space_w, space_b,
               (float*)d_out, out_size);
}

// round 10
// speedup vs baseline: 1.0543x; 1.0543x over previous
#include <cuda_runtime.h>
#include <cuda_bf16.h>
#include <cstddef>

// ---------------- problem constants ----------------
#define NN    2000     // nodes
#define BB    64       // batch
#define EE    10       // embed dim
#define HH    64       // hidden
#define DIN   2        // input dim
#define CIN   66       // Din + H
#define CG    132      // K * CIN (K=2 cheb)
#define OG    192      // gate out (3H)
#define OU    64       // update/space out (H)
#define COLSX 4224     // BB*CIN
#define COLS  8448     // 2*COLSX (X cols then Y cols)
#define BNH   8192000  // BB*NN*HH

// ---------------- device scratch (static module memory; no runtime alloc) ----------------
__device__ float d_supports[NN * NN];
__device__ float d_XY[(size_t)NN * COLS];
__device__ float d_XG[(size_t)NN * BB * CG];
__device__ float d_YG[(size_t)NN * BB * CG];
__device__ float d_Wg[(size_t)NN * CG * OG];
__device__ float d_Wu[(size_t)NN * CG * OU];
__device__ float d_Ws[(size_t)NN * CG * OU];
__device__ float d_bg[NN * OG];
__device__ float d_bu[NN * OU];
__device__ float d_bs[NN * OU];

// Host-side copies of the REAL device addresses of the weight/bias scratch.
// Passing `d_Wg` etc. directly from host code passes the HOST shadow symbol
// (silently "works" via ATS on this coherent Grace host) — must resolve via
// cudaGetSymbolAddress. Root cause of rounds 5-8.
static float* g_Wg = nullptr;
static float* g_Wu = nullptr;
static float* g_Ws = nullptr;
static float* g_bg = nullptr;
static float* g_bu = nullptr;
static float* g_bs = nullptr;

// ---------------- kernel 1: supports = softmax(relu(NE NE^T), axis=1) ----------------
__global__ __launch_bounds__(256) void supports_kernel(const float* __restrict__ ne) {
    int n = blockIdx.x;
    float nrow[EE];
#pragma unroll
    for (int d = 0; d < EE; d++) nrow[d] = ne[n * EE + d];

    __shared__ float red[256];
    int t = threadIdx.x;

    float lmax = 0.f;
    for (int m = t; m < NN; m += 256) {
        float s = 0.f;
#pragma unroll
        for (int d = 0; d < EE; d++) s += nrow[d] * __ldg(&ne[m * EE + d]);
        s = fmaxf(s, 0.f);
        d_supports[(size_t)n * NN + m] = s;
        lmax = fmaxf(lmax, s);
    }
    red[t] = lmax; __syncthreads();
    for (int o = 128; o > 0; o >>= 1) { if (t < o) red[t] = fmaxf(red[t], red[t + o]); __syncthreads(); }
    float mx = red[0];
    __syncthreads();

    float lsum = 0.f;
    for (int m = t; m < NN; m += 256) {
        float v = expf(d_supports[(size_t)n * NN + m] - mx);
        d_supports[(size_t)n * NN + m] = v;
        lsum += v;
    }
    red[t] = lsum; __syncthreads();
    for (int o = 128; o > 0; o >>= 1) { if (t < o) red[t] += red[t + o]; __syncthreads(); }
    float inv = 1.f / red[0];
    for (int m = t; m < NN; m += 256) d_supports[(size_t)n * NN + m] *= inv;
}

// ---------------- kernel 2: per-node weights / biases ----------------
__global__ __launch_bounds__(256) void mat_weights(const float* __restrict__ ne,
                                                   const float* __restrict__ pool,
                                                   float* __restrict__ W, int J, int O) {
    long total = (long)NN * J * O;
    long stride = (long)gridDim.x * blockDim.x;
    for (long idx = (long)blockIdx.x * blockDim.x + threadIdx.x; idx < total; idx += stride) {
        int o  = (int)(idx % O);
        long t2 = idx / O;
        int j  = (int)(t2 % J);
        int n  = (int)(t2 / J);
        float s = 0.f;
#pragma unroll
        for (int d = 0; d < EE; d++)
            s += ne[n * EE + d] * __ldg(&pool[((size_t)d * J + j) * O + o]);
        W[idx] = s;
    }
}

// ---------------- kernel 3: pack inputs node-major ----------------
__global__ __launch_bounds__(256) void pack_kernel(const float* __restrict__ x,
                                                   const float* __restrict__ y,
                                                   const float* __restrict__ state,
                                                   const float* __restrict__ lstate) {
    int total = NN * BB * CIN;
    int stride = gridDim.x * blockDim.x;
    for (int idx = blockIdx.x * blockDim.x + threadIdx.x; idx < total; idx += stride) {
        int i = idx % CIN;
        int t2 = idx / CIN;
        int b = t2 % BB;
        int n = t2 / BB;
        float vx, vy;
        if (i < DIN) {
            vx = x[((size_t)b * NN + n) * DIN + i];
            vy = y[((size_t)b * NN + n) * DIN + i];
        } else {
            vx = state[((size_t)b * NN + n) * HH + (i - DIN)];
            vy = lstate[((size_t)b * NN + n) * HH + (i - DIN)];
        }
        d_XG[((size_t)n * BB + b) * CG + i] = vx;
        d_YG[((size_t)n * BB + b) * CG + i] = vy;
        d_XY[(size_t)n * COLS + b * CIN + i] = vx;
        d_XY[(size_t)n * COLS + COLSX + b * CIN + i] = vy;
    }
}

// ---------------- kernel 4: SGEMM (double-buffered, BK=16, reg-prefetch) ----------------
#define BM 128
#define BN 128
#define BK 16
__global__ __launch_bounds__(256) void sgemm3() {
    __shared__ float As[2][BK][BM + 4];
    __shared__ float Bs[2][BK][BN];

    int row0 = blockIdx.y * BM;
    int col0 = blockIdx.x * BN;
    int tid = threadIdx.x;

    int arow = tid >> 2;          // 0..63
    int acol = (tid & 3) * 4;     // 0,4,8,12
    int brow = tid >> 5;          // 0..7
    int bcol = (tid & 31) * 4;    // 0..124
    int tx = tid & 15, ty = tid >> 4;

    // prologue: tile k0=0 into buffer 0
    {
#pragma unroll
        for (int rr = 0; rr < 2; rr++) {
            int r = arow + rr * 64;
            int gr = row0 + r;
            float4 v = make_float4(0.f, 0.f, 0.f, 0.f);
            if (gr < NN) v = *(const float4*)&d_supports[(size_t)gr * NN + acol];
            As[0][acol + 0][r] = v.x; As[0][acol + 1][r] = v.y;
            As[0][acol + 2][r] = v.z; As[0][acol + 3][r] = v.w;
            int rB = brow + rr * 8;
            *(float4*)&Bs[0][rB][bcol] = *(const float4*)&d_XY[(size_t)rB * COLS + col0 + bcol];
        }
    }
    __syncthreads();

    float acc[8][8];
#pragma unroll
    for (int i = 0; i < 8; i++)
#pragma unroll
        for (int j = 0; j < 8; j++) acc[i][j] = 0.f;

    int cur = 0;
    for (int k0 = 0; k0 < NN; k0 += BK) {
        int kn = k0 + BK;
        float4 ra0, ra1, rb0, rb1;
        bool more = (kn < NN);
        if (more) {
            int gr0 = row0 + arow;
            int gr1 = gr0 + 64;
            ra0 = (gr0 < NN) ? *(const float4*)&d_supports[(size_t)gr0 * NN + kn + acol]
                             : make_float4(0.f, 0.f, 0.f, 0.f);
            ra1 = (gr1 < NN) ? *(const float4*)&d_supports[(size_t)gr1 * NN + kn + acol]
                             : make_float4(0.f, 0.f, 0.f, 0.f);
            rb0 = *(const float4*)&d_XY[(size_t)(kn + brow) * COLS + col0 + bcol];
            rb1 = *(const float4*)&d_XY[(size_t)(kn + brow + 8) * COLS + col0 + bcol];
        }
#pragma unroll
        for (int kk = 0; kk < BK; kk++) {
            float4 a0 = *(const float4*)&As[cur][kk][ty * 8];
            float4 a1 = *(const float4*)&As[cur][kk][ty * 8 + 4];
            float4 b0 = *(const float4*)&Bs[cur][kk][tx * 8];
            float4 b1 = *(const float4*)&Bs[cur][kk][tx * 8 + 4];
            acc[0][0] = fmaf(a0.x, b0.x, acc[0][0]); acc[0][1] = fmaf(a0.x, b0.y, acc[0][1]);
            acc[0][2] = fmaf(a0.x, b0.z, acc[0][2]); acc[0][3] = fmaf(a0.x, b0.w, acc[0][3]);
            acc[0][4] = fmaf(a0.x, b1.x, acc[0][4]); acc[0][5] = fmaf(a0.x, b1.y, acc[0][5]);
            acc[0][6] = fmaf(a0.x, b1.z, acc[0][6]); acc[0][7] = fmaf(a0.x, b1.w, acc[0][7]);
            acc[1][0] = fmaf(a0.y, b0.x, acc[1][0]); acc[1][1] = fmaf(a0.y, b0.y, acc[1][1]);
            acc[1][2] = fmaf(a0.y, b0.z, acc[1][2]); acc[1][3] = fmaf(a0.y, b0.w, acc[1][3]);
            acc[1][4] = fmaf(a0.y, b1.x, acc[1][4]); acc[1][5] = fmaf(a0.y, b1.y, acc[1][5]);
            acc[1][6] = fmaf(a0.y, b1.z, acc[1][6]); acc[1][7] = fmaf(a0.y, b1.w, acc[1][7]);
            acc[2][0] = fmaf(a0.z, b0.x, acc[2][0]); acc[2][1] = fmaf(a0.z, b0.y, acc[2][1]);
            acc[2][2] = fmaf(a0.z, b0.z, acc[2][2]); acc[2][3] = fmaf(a0.z, b0.w, acc[2][3]);
            acc[2][4] = fmaf(a0.z, b1.x, acc[2][4]); acc[2][5] = fmaf(a0.z, b1.y, acc[2][5]);
            acc[2][6] = fmaf(a0.z, b1.z, acc[2][6]); acc[2][7] = fmaf(a0.z, b1.w, acc[2][7]);
            acc[3][0] = fmaf(a0.w, b0.x, acc[3][0]); acc[3][1] = fmaf(a0.w, b0.y, acc[3][1]);
            acc[3][2] = fmaf(a0.w, b0.z, acc[3][2]); acc[3][3] = fmaf(a0.w, b0.w, acc[3][3]);
            acc[3][4] = fmaf(a0.w, b1.x, acc[3][4]); acc[3][5] = fmaf(a0.w, b1.y, acc[3][5]);
            acc[3][6] = fmaf(a0.w, b1.z, acc[3][6]); acc[3][7] = fmaf(a0.w, b1.w, acc[3][7]);
            acc[4][0] = fmaf(a1.x, b0.x, acc[4][0]); acc[4][1] = fmaf(a1.x, b0.y, acc[4][1]);
            acc[4][2] = fmaf(a1.x, b0.z, acc[4][2]); acc[4][3] = fmaf(a1.x, b0.w, acc[4][3]);
            acc[4][4] = fmaf(a1.x, b1.x, acc[4][4]); acc[4][5] = fmaf(a1.x, b1.y, acc[4][5]);
            acc[4][6] = fmaf(a1.x, b1.z, acc[4][6]); acc[4][7] = fmaf(a1.x, b1.w, acc[4][7]);
            acc[5][0] = fmaf(a1.y, b0.x, acc[5][0]); acc[5][1] = fmaf(a1.y, b0.y, acc[5][1]);
            acc[5][2] = fmaf(a1.y, b0.z, acc[5][2]); acc[5][3] = fmaf(a1.y, b0.w, acc[5][3]);
            acc[5][4] = fmaf(a1.y, b1.x, acc[5][4]); acc[5][5] = fmaf(a1.y, b1.y, acc[5][5]);
            acc[5][6] = fmaf(a1.y, b1.z, acc[5][6]); acc[5][7] = fmaf(a1.y, b1.w, acc[5][7]);
            acc[6][0] = fmaf(a1.z, b0.x, acc[6][0]); acc[6][1] = fmaf(a1.z, b0.y, acc[6][1]);
            acc[6][2] = fmaf(a1.z, b0.z, acc[6][2]); acc[6][3] = fmaf(a1.z, b0.w, acc[6][3]);
            acc[6][4] = fmaf(a1.z, b1.x, acc[6][4]); acc[6][5] = fmaf(a1.z, b1.y, acc[6][5]);
            acc[6][6] = fmaf(a1.z, b1.z, acc[6][6]); acc[6][7] = fmaf(a1.z, b1.w, acc[6][7]);
            acc[7][0] = fmaf(a1.w, b0.x, acc[7][0]); acc[7][1] = fmaf(a1.w, b0.y, acc[7][1]);
            acc[7][2] = fmaf(a1.w, b0.z, acc[7][2]); acc[7][3] = fmaf(a1.w, b0.w, acc[7][3]);
            acc[7][4] = fmaf(a1.w, b1.x, acc[7][4]); acc[7][5] = fmaf(a1.w, b1.y, acc[7][5]);
            acc[7][6] = fmaf(a1.w, b1.z, acc[7][6]); acc[7][7] = fmaf(a1.w, b1.w, acc[7][7]);
        }
        if (more) {
            int nxt = cur ^ 1;
            As[nxt][acol + 0][arow] = ra0.x; As[nxt][acol + 1][arow] = ra0.y;
            As[nxt][acol + 2][arow] = ra0.z; As[nxt][acol + 3][arow] = ra0.w;
            As[nxt][acol + 0][arow + 64] = ra1.x; As[nxt][acol + 1][arow + 64] = ra1.y;
            As[nxt][acol + 2][arow + 64] = ra1.z; As[nxt][acol + 3][arow + 64] = ra1.w;
            *(float4*)&Bs[nxt][brow][bcol]     = rb0;
            *(float4*)&Bs[nxt][brow + 8][bcol] = rb1;
            __syncthreads();
            cur = nxt;
        }
    }

    // scatter C into diffusion halves of XG / YG
#pragma unroll
    for (int i = 0; i < 8; i++) {
        int n = row0 + ty * 8 + i;
        if (n >= NN) continue;
#pragma unroll
        for (int j = 0; j < 8; j++) {
            int c = col0 + tx * 8 + j;
            float v = acc[i][j];
            float* dst;
            int cc = c;
            if (cc < COLSX) { dst = d_XG; }
            else            { dst = d_YG; cc -= COLSX; }
            int b = cc / CIN, ii = cc % CIN;
            dst[((size_t)n * BB + b) * CG + CIN + ii] = v;
        }
    }
}

// ---------------- kernel 5: per-node matmuls + LSTM ----------------
__device__ __forceinline__ float sigmoidf_(float v) { return 1.f / (1.f + expf(-v)); }

__global__ __launch_bounds__(1024) void final2(const float* __restrict__ cell,
                                               float* __restrict__ out, int out_elems) {
    extern __shared__ float smem[];
    float* sx = smem;
    float* sy = smem + BB * CG;

    int n = blockIdx.x;
    int t = threadIdx.x;

    const float4* gx = (const float4*)&d_XG[(size_t)n * BB * CG];
    const float4* gy = (const float4*)&d_YG[(size_t)n * BB * CG];
    for (int i = t; i < BB * CG / 4; i += 1024) {
        ((float4*)sx)[i] = gx[i];
        ((float4*)sy)[i] = gy[i];
    }
    __syncthreads();

    int ou = t & 63;
    int b0 = (t >> 6) * 4;

    const float* wg = d_Wg + (size_t)n * CG * OG;
    const float* wu = d_Wu + (size_t)n * CG * OU;
    const float* ws = d_Ws + (size_t)n * CG * OU;

    float af[4] = {0.f, 0.f, 0.f, 0.f};
    float ai[4] = {0.f, 0.f, 0.f, 0.f};
    float ao[4] = {0.f, 0.f, 0.f, 0.f};
    float ag[4] = {0.f, 0.f, 0.f, 0.f};
    float as_[4] = {0.f, 0.f, 0.f, 0.f};

    for (int j = 0; j < CG; j++) {
        float wf  = __ldg(&wg[j * OG + ou]);
        float wi  = __ldg(&wg[j * OG + 64 + ou]);
        float wo  = __ldg(&wg[j * OG + 128 + ou]);
        float wuv = __ldg(&wu[j * OU + ou]);
        float wsv = __ldg(&ws[j * OU + ou]);
#pragma unroll
        for (int r = 0; r < 4; r++) {
            float xv = sx[(b0 + r) * CG + j];
            float yv = sy[(b0 + r) * CG + j];
            af[r]  = fmaf(wf,  xv, af[r]);
            ai[r]  = fmaf(wi,  xv, ai[r]);
            ao[r]  = fmaf(wo,  xv, ao[r]);
            ag[r]  = fmaf(wuv, xv, ag[r]);
            as_[r] = fmaf(wsv, yv, as_[r]);
        }
    }

    float bf = d_bg[n * OG + ou];
    float bi = d_bg[n * OG + 64 + ou];
    float bo = d_bg[n * OG + 128 + ou];
    float bu = d_bu[n * OU + ou];
    float bs = d_bs[n * OU + ou];

#pragma unroll
    for (int r = 0; r < 4; r++) {
        int b = b0 + r;
        float f  = sigmoidf_(af[r] + bf);
        float i2 = sigmoidf_(ai[r] + bi);
        float o2 = sigmoidf_(ao[r] + bo);
        float g  = tanhf(ag[r] + bu);
        float s  = sigmoidf_(as_[r] + bs);
        size_t base = ((size_t)b * NN + n) * HH + ou;
        float c = fmaf(f, cell[base], i2 * g);
        out[base] = o2 * tanhf(c);                                        // h
        if (BNH + base < (size_t)out_elems)     out[BNH + base] = c;      // c
        if (2 * BNH + base < (size_t)out_elems) out[2 * BNH + base] = s;  // new_last_state
    }
}

// ---------------- dummy kernel: force a generous local-memory pool ----------------
__global__ __launch_bounds__(256) void lmem_warm_kernel(float* sink) {
    volatile float buf[512];
    for (int i = 0; i < 512; i++) buf[i] = (float)(i ^ (int)threadIdx.x);
    float s = 0.f;
    for (int i = 0; i < 512; i++) s += buf[i];
    if (s < -1e30f) sink[0] = s;
}

// ---------------- full launch sequence (shared by warmup + real) ----------------
static void launch_all(const float* x, const float* y, const float* state,
                       const float* cell, const float* lstate, const float* ne,
                       const float* gate_w, const float* gate_b,
                       const float* update_w, const float* update_b,
                       const float* space_w, const float* space_b,
                       float* out, int out_elems) {
    supports_kernel<<<NN, 256>>>(ne);
    long totG = (long)NN * CG * OG;
    long totU = (long)NN * CG * OU;
    mat_weights<<<(int)((totG + 255) / 256), 256>>>(ne, gate_w,   g_Wg, CG, OG);
    mat_weights<<<(int)((totU + 255) / 256), 256>>>(ne, update_w, g_Wu, CG, OU);
    mat_weights<<<(int)((totU + 255) / 256), 256>>>(ne, space_w,  g_Ws, CG, OU);
    mat_weights<<<(NN * OG + 255) / 256, 256>>>(ne, gate_b,   g_bg, 1, OG);
    mat_weights<<<(NN * OU + 255) / 256, 256>>>(ne, update_b, g_bu, 1, OU);
    mat_weights<<<(NN * OU + 255) / 256, 256>>>(ne, space_b,  g_bs, 1, OU);
    pack_kernel<<<(NN * BB * CIN + 255) / 256, 256>>>(x, y, state, lstate);
    sgemm3<<<dim3(COLS / BN, (NN + BM - 1) / BM), 256>>>();
    final2<<<NN, 1024, 2 * BB * CG * (int)sizeof(float)>>>(cell, out, out_elems);
}

// ---------------- static-init warmup (pre-main, pre-checkpoint) ----------------
namespace {
struct Warmup {
    Warmup() {
        cudaFuncSetAttribute(final2, cudaFuncAttributeMaxDynamicSharedMemorySize,
                             2 * BB * CG * (int)sizeof(float));
        cudaGetSymbolAddress((void**)&g_Wg, d_Wg);
        cudaGetSymbolAddress((void**)&g_Wu, d_Wu);
        cudaGetSymbolAddress((void**)&g_Ws, d_Ws);
        cudaGetSymbolAddress((void**)&g_bg, d_bg);
        cudaGetSymbolAddress((void**)&g_bu, d_bu);
        cudaGetSymbolAddress((void**)&g_bs, d_bs);
        float* scratchA = nullptr;   // d_XY: 16.9M floats
        float* scratchB = nullptr;   // d_Wg: 50.7M floats (as warmup out buffer)
        cudaGetSymbolAddress((void**)&scratchA, d_XY);
        cudaGetSymbolAddress((void**)&scratchB, d_Wg);
        if (scratchA && scratchB && g_Wg) {
            lmem_warm_kernel<<<592, 256>>>(scratchA);
            launch_all(scratchA, scratchA, scratchA, scratchA, scratchA, scratchA,
                       scratchA, scratchA, scratchA, scratchA, scratchA, scratchA,
                       scratchB, 3 * BNH);
        }
        cudaDeviceSynchronize();
        cudaGetLastError();
    }
};
Warmup g_warmup;
}  // namespace

// ---------------- launch (inputs in setup_inputs dict order) ----------------
extern "C" void kernel_launch(void* const* d_in, const int* in_sizes, int n_in,
                              void* d_out, int out_size) {
    const float* x        = (const float*)d_in[0];
    const float* y        = (const float*)d_in[1];
    const float* state    = (const float*)d_in[2];
    const float* cell     = (const float*)d_in[3];
    const float* lstate   = (const float*)d_in[4];
    const float* ne       = (const float*)d_in[5];
    const float* gate_w   = (const float*)d_in[6];
    const float* gate_b   = (const float*)d_in[7];
    const float* update_w = (const float*)d_in[8];
    const float* update_b = (const float*)d_in[9];
    const float* space_w  = (const float*)d_in[10];
    const float* space_b  = (const float*)d_in[11];

    launch_all(x, y, state, cell, lstate, ne,
               gate_w, gate_b, update_w, update_b, space_w, space_b,
               (float*)d_out, out_size);
}

// round 12
// speedup vs baseline: 1.1938x; 1.1323x over previous
#include <cuda_runtime.h>
#include <cuda_bf16.h>
#include <cstddef>
#include <cstdint>

// ---------------- problem constants ----------------
#define NN    2000     // nodes
#define BB    64       // batch
#define EE    10       // embed dim
#define HH    64       // hidden
#define DIN   2        // input dim
#define CIN   66       // Din + H
#define CG    132      // K * CIN (K=2 cheb)
#define OG    192      // gate out (3H)
#define OU    64       // update/space out (H)
#define COLSX 4224     // BB*CIN
#define COLS  8448     // 2*COLSX (X cols then Y cols)
#define BNH   8192000  // BB*NN*HH
#define KPAD  2048     // K dim padded for tensor GEMM (zero-filled tail)

// ---------------- device scratch (static module memory; no runtime alloc) ----------------
__device__ float d_supports[NN * NN];                       // fp32 workspace for softmax
__device__ __nv_bfloat16 d_s_hi[(size_t)NN * KPAD];         // supports hi (cols >=2000 stay zero)
__device__ __nv_bfloat16 d_s_lo[(size_t)NN * KPAD];         // supports lo
__device__ __nv_bfloat16 d_xy_hi[(size_t)KPAD * COLS];      // XY hi (rows >=2000 stay zero)
__device__ __nv_bfloat16 d_xy_lo[(size_t)KPAD * COLS];      // XY lo
__device__ float d_XY[(size_t)NN * COLS];                   // retained as warmup scratch
__device__ float d_XG[(size_t)NN * BB * CG];
__device__ float d_YG[(size_t)NN * BB * CG];
__device__ float d_Wg[(size_t)NN * CG * OG];
__device__ float d_Wu[(size_t)NN * CG * OU];
__device__ float d_Ws[(size_t)NN * CG * OU];
__device__ float d_bg[NN * OG];
__device__ float d_bu[NN * OU];
__device__ float d_bs[NN * OU];

// Real device addresses (cudaGetSymbolAddress) for args passed from host.
// Raw __device__ symbols from host code are HOST shadow addresses (ATS trap
// on this coherent Grace host) — root cause of rounds 5-8.
static float* g_Wg = nullptr;
static float* g_Wu = nullptr;
static float* g_Ws = nullptr;
static float* g_bg = nullptr;
static float* g_bu = nullptr;
static float* g_bs = nullptr;

// ---------------- kernel 1: supports = softmax(relu(NE NE^T), axis=1) + bf16 split ----
__global__ __launch_bounds__(256) void supports_kernel(const float* __restrict__ ne) {
    int n = blockIdx.x;
    float nrow[EE];
#pragma unroll
    for (int d = 0; d < EE; d++) nrow[d] = ne[n * EE + d];

    __shared__ float red[256];
    int t = threadIdx.x;

    float lmax = 0.f;
    for (int m = t; m < NN; m += 256) {
        float s = 0.f;
#pragma unroll
        for (int d = 0; d < EE; d++) s += nrow[d] * __ldg(&ne[m * EE + d]);
        s = fmaxf(s, 0.f);
        d_supports[(size_t)n * NN + m] = s;
        lmax = fmaxf(lmax, s);
    }
    red[t] = lmax; __syncthreads();
    for (int o = 128; o > 0; o >>= 1) { if (t < o) red[t] = fmaxf(red[t], red[t + o]); __syncthreads(); }
    float mx = red[0];
    __syncthreads();

    float lsum = 0.f;
    for (int m = t; m < NN; m += 256) {
        float v = expf(d_supports[(size_t)n * NN + m] - mx);
        d_supports[(size_t)n * NN + m] = v;
        lsum += v;
    }
    red[t] = lsum; __syncthreads();
    for (int o = 128; o > 0; o >>= 1) { if (t < o) red[t] += red[t + o]; __syncthreads(); }
    float inv = 1.f / red[0];
    for (int m = t; m < NN; m += 256) {
        float v = d_supports[(size_t)n * NN + m] * inv;
        __nv_bfloat16 h = __float2bfloat16(v);
        d_s_hi[(size_t)n * KPAD + m] = h;
        d_s_lo[(size_t)n * KPAD + m] = __float2bfloat16(v - __bfloat162float(h));
    }
}

// ---------------- kernel 2: per-node weights / biases ----------------
__global__ __launch_bounds__(256) void mat_weights(const float* __restrict__ ne,
                                                   const float* __restrict__ pool,
                                                   float* __restrict__ W, int J, int O) {
    long total = (long)NN * J * O;
    long stride = (long)gridDim.x * blockDim.x;
    for (long idx = (long)blockIdx.x * blockDim.x + threadIdx.x; idx < total; idx += stride) {
        int o  = (int)(idx % O);
        long t2 = idx / O;
        int j  = (int)(t2 % J);
        int n  = (int)(t2 / J);
        float s = 0.f;
#pragma unroll
        for (int d = 0; d < EE; d++)
            s += ne[n * EE + d] * __ldg(&pool[((size_t)d * J + j) * O + o]);
        W[idx] = s;
    }
}

// ---------------- kernel 3: pack inputs node-major (fp32 for final2, bf16 hi/lo for GEMM) ----
__global__ __launch_bounds__(256) void pack_kernel(const float* __restrict__ x,
                                                   const float* __restrict__ y,
                                                   const float* __restrict__ state,
                                                   const float* __restrict__ lstate) {
    int total = NN * BB * CIN;
    int stride = gridDim.x * blockDim.x;
    for (int idx = blockIdx.x * blockDim.x + threadIdx.x; idx < total; idx += stride) {
        int i = idx % CIN;
        int t2 = idx / CIN;
        int b = t2 % BB;
        int n = t2 / BB;
        float vx, vy;
        if (i < DIN) {
            vx = x[((size_t)b * NN + n) * DIN + i];
            vy = y[((size_t)b * NN + n) * DIN + i];
        } else {
            vx = state[((size_t)b * NN + n) * HH + (i - DIN)];
            vy = lstate[((size_t)b * NN + n) * HH + (i - DIN)];
        }
        d_XG[((size_t)n * BB + b) * CG + i] = vx;
        d_YG[((size_t)n * BB + b) * CG + i] = vy;
        int cx = b * CIN + i;
        __nv_bfloat16 hx = __float2bfloat16(vx);
        __nv_bfloat16 hy = __float2bfloat16(vy);
        d_xy_hi[(size_t)n * COLS + cx] = hx;
        d_xy_lo[(size_t)n * COLS + cx] = __float2bfloat16(vx - __bfloat162float(hx));
        d_xy_hi[(size_t)n * COLS + COLSX + cx] = hy;
        d_xy_lo[(size_t)n * COLS + COLSX + cx] = __float2bfloat16(vy - __bfloat162float(hy));
    }
}

// ---------------- kernel 4: tensor-core GEMM (bf16x3 split, m16n8k16 HMMA) --------------
// C[n,c] = sum_m S[n,m]*XY[m,c], fp32 accum via Ahi*Bhi + Ahi*Blo + Alo*Bhi.
#define PA 40   // A smem pitch (bf16): conflict-free fragment loads
#define PB 34   // B smem pitch (bf16): 2-way worst case on transpose store/frag load

__device__ __forceinline__ void mma16816(float (&c)[4], const uint32_t (&a)[4],
                                         uint32_t b0, uint32_t b1) {
    asm volatile(
        "mma.sync.aligned.m16n8k16.row.col.f32.bf16.bf16.f32 "
        "{%0,%1,%2,%3}, {%4,%5,%6,%7}, {%8,%9}, {%0,%1,%2,%3};"
        : "+f"(c[0]), "+f"(c[1]), "+f"(c[2]), "+f"(c[3])
        : "r"(a[0]), "r"(a[1]), "r"(a[2]), "r"(a[3]), "r"(b0), "r"(b1));
}

__global__ __launch_bounds__(256) void sgemm_tc() {
    __shared__ __nv_bfloat16 As_hi[128 * PA];   // [r][k] k<32
    __shared__ __nv_bfloat16 As_lo[128 * PA];
    __shared__ __nv_bfloat16 Bs_hi[128 * PB];   // [c][k] transposed, k<32
    __shared__ __nv_bfloat16 Bs_lo[128 * PB];

    int row0 = blockIdx.y * 128;
    int col0 = blockIdx.x * 128;
    int tid = threadIdx.x;
    int warp = tid >> 5, lane = tid & 31;
    int g = lane >> 2, tg = lane & 3;
    int warpM = warp >> 1, warpN = warp & 1;   // 4 x 2 warps over 128x128

    float acc[2][8][4];
#pragma unroll
    for (int mt = 0; mt < 2; mt++)
#pragma unroll
        for (int nt = 0; nt < 8; nt++)
#pragma unroll
            for (int q = 0; q < 4; q++) acc[mt][nt][q] = 0.f;

    const uint32_t* shi32 = (const uint32_t*)d_s_hi;
    const uint32_t* slo32 = (const uint32_t*)d_s_lo;

    for (int chunk = 0; chunk < KPAD / 32; chunk++) {
        int k0 = chunk * 32;
        if (chunk) __syncthreads();   // previous compute done before overwrite

        // ---- load A tile [128 rows][32 k] (hi+lo), u32 = 2 bf16 along k ----
#pragma unroll
        for (int i = 0; i < 8; i++) {
            int idx = i * 256 + tid;        // 0..2047
            int r = idx >> 4;               // 0..127
            int kk = idx & 15;              // u32 index within 32-k row
            int gr = row0 + r;
            uint32_t vh = 0u, vl = 0u;
            if (gr < NN) {
                size_t off = (size_t)gr * (KPAD / 2) + (k0 >> 1) + kk;
                vh = shi32[off];
                vl = slo32[off];
            }
            *(uint32_t*)&As_hi[r * PA + kk * 2] = vh;
            *(uint32_t*)&As_lo[r * PA + kk * 2] = vl;
        }
        // ---- load B tile [32 k][128 c] transposed into [c][k] (hi+lo) ----
#pragma unroll
        for (int i = 0; i < 8; i++) {
            int idx = i * 256 + tid;        // 0..2047
            int k = idx >> 6;               // 0..31
            int j = idx & 63;               // bf162 index within 128-c row
            int cc = j * 2;
            size_t off = (size_t)(k0 + k) * COLS + col0 + cc;
            __nv_bfloat162 vh = *(const __nv_bfloat162*)&d_xy_hi[off];
            __nv_bfloat162 vl = *(const __nv_bfloat162*)&d_xy_lo[off];
            Bs_hi[cc * PB + k] = vh.x; Bs_hi[(cc + 1) * PB + k] = vh.y;
            Bs_lo[cc * PB + k] = vl.x; Bs_lo[(cc + 1) * PB + k] = vl.y;
        }
        __syncthreads();

        // ---- compute: 2 k16-steps ----
#pragma unroll
        for (int kk16 = 0; kk16 < 32; kk16 += 16) {
            uint32_t ah[2][4], al[2][4];
#pragma unroll
            for (int mt = 0; mt < 2; mt++) {
                int row = warpM * 32 + mt * 16 + g;
                int base = row * PA + kk16 + tg * 2;
                ah[mt][0] = *(const uint32_t*)&As_hi[base];
                ah[mt][1] = *(const uint32_t*)&As_hi[base + 8 * PA];
                ah[mt][2] = *(const uint32_t*)&As_hi[base + 8];
                ah[mt][3] = *(const uint32_t*)&As_hi[base + 8 * PA + 8];
                al[mt][0] = *(const uint32_t*)&As_lo[base];
                al[mt][1] = *(const uint32_t*)&As_lo[base + 8 * PA];
                al[mt][2] = *(const uint32_t*)&As_lo[base + 8];
                al[mt][3] = *(const uint32_t*)&As_lo[base + 8 * PA + 8];
            }
#pragma unroll
            for (int nt = 0; nt < 8; nt++) {
                int colr = warpN * 64 + nt * 8 + g;
                int bb = colr * PB + kk16 + tg * 2;
                uint32_t bh0 = *(const uint32_t*)&Bs_hi[bb];
                uint32_t bh1 = *(const uint32_t*)&Bs_hi[bb + 8];
                uint32_t bl0 = *(const uint32_t*)&Bs_lo[bb];
                uint32_t bl1 = *(const uint32_t*)&Bs_lo[bb + 8];
#pragma unroll
                for (int mt = 0; mt < 2; mt++) {
                    mma16816(acc[mt][nt], ah[mt], bh0, bh1);
                    mma16816(acc[mt][nt], ah[mt], bl0, bl1);
                    mma16816(acc[mt][nt], al[mt], bh0, bh1);
                }
            }
        }
    }

    // ---- epilogue: scatter C into diffusion halves of XG/YG ----
#pragma unroll
    for (int mt = 0; mt < 2; mt++) {
#pragma unroll
        for (int nt = 0; nt < 8; nt++) {
            int r1 = row0 + warpM * 32 + mt * 16 + g;
            int c1 = col0 + warpN * 64 + nt * 8 + tg * 2;
#pragma unroll
            for (int q = 0; q < 4; q++) {
                int n = r1 + (q >> 1) * 8;
                int c = c1 + (q & 1);
                if (n >= NN) continue;
                float v = acc[mt][nt][q];
                float* dst;
                int cc = c;
                if (cc < COLSX) { dst = d_XG; }
                else            { dst = d_YG; cc -= COLSX; }
                int b = cc / CIN, ii = cc % CIN;
                dst[((size_t)n * BB + b) * CG + CIN + ii] = v;
            }
        }
    }
}

// ---------------- kernel 5: per-node matmuls + LSTM ----------------
__device__ __forceinline__ float sigmoidf_(float v) { return 1.f / (1.f + expf(-v)); }

__global__ __launch_bounds__(1024) void final2(const float* __restrict__ cell,
                                               float* __restrict__ out, int out_elems) {
    extern __shared__ float smem[];
    float* sx = smem;
    float* sy = smem + BB * CG;

    int n = blockIdx.x;
    int t = threadIdx.x;

    const float4* gx = (const float4*)&d_XG[(size_t)n * BB * CG];
    const float4* gy = (const float4*)&d_YG[(size_t)n * BB * CG];
    for (int i = t; i < BB * CG / 4; i += 1024) {
        ((float4*)sx)[i] = gx[i];
        ((float4*)sy)[i] = gy[i];
    }
    __syncthreads();

    int ou = t & 63;
    int b0 = (t >> 6) * 4;

    const float* wg = d_Wg + (size_t)n * CG * OG;
    const float* wu = d_Wu + (size_t)n * CG * OU;
    const float* ws = d_Ws + (size_t)n * CG * OU;

    float af[4] = {0.f, 0.f, 0.f, 0.f};
    float ai[4] = {0.f, 0.f, 0.f, 0.f};
    float ao[4] = {0.f, 0.f, 0.f, 0.f};
    float ag[4] = {0.f, 0.f, 0.f, 0.f};
    float as_[4] = {0.f, 0.f, 0.f, 0.f};

    for (int j = 0; j < CG; j++) {
        float wf  = __ldg(&wg[j * OG + ou]);
        float wi  = __ldg(&wg[j * OG + 64 + ou]);
        float wo  = __ldg(&wg[j * OG + 128 + ou]);
        float wuv = __ldg(&wu[j * OU + ou]);
        float wsv = __ldg(&ws[j * OU + ou]);
#pragma unroll
        for (int r = 0; r < 4; r++) {
            float xv = sx[(b0 + r) * CG + j];
            float yv = sy[(b0 + r) * CG + j];
            af[r]  = fmaf(wf,  xv, af[r]);
            ai[r]  = fmaf(wi,  xv, ai[r]);
            ao[r]  = fmaf(wo,  xv, ao[r]);
            ag[r]  = fmaf(wuv, xv, ag[r]);
            as_[r] = fmaf(wsv, yv, as_[r]);
        }
    }

    float bf = d_bg[n * OG + ou];
    float bi = d_bg[n * OG + 64 + ou];
    float bo = d_bg[n * OG + 128 + ou];
    float bu = d_bu[n * OU + ou];
    float bs = d_bs[n * OU + ou];

#pragma unroll
    for (int r = 0; r < 4; r++) {
        int b = b0 + r;
        float f  = sigmoidf_(af[r] + bf);
        float i2 = sigmoidf_(ai[r] + bi);
        float o2 = sigmoidf_(ao[r] + bo);
        float g  = tanhf(ag[r] + bu);
        float s  = sigmoidf_(as_[r] + bs);
        size_t base = ((size_t)b * NN + n) * HH + ou;
        float c = fmaf(f, cell[base], i2 * g);
        out[base] = o2 * tanhf(c);                                        // h
        if (BNH + base < (size_t)out_elems)     out[BNH + base] = c;      // c
        if (2 * BNH + base < (size_t)out_elems) out[2 * BNH + base] = s;  // new_last_state
    }
}

// ---------------- dummy kernel: force a generous local-memory pool ----------------
__global__ __launch_bounds__(256) void lmem_warm_kernel(float* sink) {
    volatile float buf[512];
    for (int i = 0; i < 512; i++) buf[i] = (float)(i ^ (int)threadIdx.x);
    float s = 0.f;
    for (int i = 0; i < 512; i++) s += buf[i];
    if (s < -1e30f) sink[0] = s;
}

// ---------------- full launch sequence (shared by warmup + real) ----------------
static void launch_all(const float* x, const float* y, const float* state,
                       const float* cell, const float* lstate, const float* ne,
                       const float* gate_w, const float* gate_b,
                       const float* update_w, const float* update_b,
                       const float* space_w, const float* space_b,
                       float* out, int out_elems) {
    supports_kernel<<<NN, 256>>>(ne);
    long totG = (long)NN * CG * OG;
    long totU = (long)NN * CG * OU;
    mat_weights<<<(int)((totG + 255) / 256), 256>>>(ne, gate_w,   g_Wg, CG, OG);
    mat_weights<<<(int)((totU + 255) / 256), 256>>>(ne, update_w, g_Wu, CG, OU);
    mat_weights<<<(int)((totU + 255) / 256), 256>>>(ne, space_w,  g_Ws, CG, OU);
    mat_weights<<<(NN * OG + 255) / 256, 256>>>(ne, gate_b,   g_bg, 1, OG);
    mat_weights<<<(NN * OU + 255) / 256, 256>>>(ne, update_b, g_bu, 1, OU);
    mat_weights<<<(NN * OU + 255) / 256, 256>>>(ne, space_b,  g_bs, 1, OU);
    pack_kernel<<<(NN * BB * CIN + 255) / 256, 256>>>(x, y, state, lstate);
    sgemm_tc<<<dim3(COLS / 128, (NN + 127) / 128), 256>>>();
    final2<<<NN, 1024, 2 * BB * CG * (int)sizeof(float)>>>(cell, out, out_elems);
}

// ---------------- static-init warmup (pre-main, pre-checkpoint) ----------------
namespace {
struct Warmup {
    Warmup() {
        cudaFuncSetAttribute(final2, cudaFuncAttributeMaxDynamicSharedMemorySize,
                             2 * BB * CG * (int)sizeof(float));
        cudaGetSymbolAddress((void**)&g_Wg, d_Wg);
        cudaGetSymbolAddress((void**)&g_Wu, d_Wu);
        cudaGetSymbolAddress((void**)&g_Ws, d_Ws);
        cudaGetSymbolAddress((void**)&g_bg, d_bg);
        cudaGetSymbolAddress((void**)&g_bu, d_bu);
        cudaGetSymbolAddress((void**)&g_bs, d_bs);
        float* scratchA = nullptr;   // d_XY: 16.9M floats (garbage inputs OK)
        float* scratchB = nullptr;   // d_Wg: 50.7M floats (warmup out buffer)
        cudaGetSymbolAddress((void**)&scratchA, d_XY);
        cudaGetSymbolAddress((void**)&scratchB, d_Wg);
        if (scratchA && scratchB && g_Wg) {
            lmem_warm_kernel<<<592, 256>>>(scratchA);
            launch_all(scratchA, scratchA, scratchA, scratchA, scratchA, scratchA,
                       scratchA, scratchA, scratchA, scratchA, scratchA, scratchA,
                       scratchB, 3 * BNH);
        }
        cudaDeviceSynchronize();
        cudaGetLastError();
    }
};
Warmup g_warmup;
}  // namespace

// ---------------- launch (inputs in setup_inputs dict order) ----------------
extern "C" void kernel_launch(void* const* d_in, const int* in_sizes, int n_in,
                              void* d_out, int out_size) {
    const float* x        = (const float*)d_in[0];
    const float* y        = (const float*)d_in[1];
    const float* state    = (const float*)d_in[2];
    const float* cell     = (const float*)d_in[3];
    const float* lstate   = (const float*)d_in[4];
    const float* ne       = (const float*)d_in[5];
    const float* gate_w   = (const float*)d_in[6];
    const float* gate_b   = (const float*)d_in[7];
    const float* update_w = (const float*)d_in[8];
    const float* update_b = (const float*)d_in[9];
    const float* space_w  = (const float*)d_in[10];
    const float* space_b  = (const float*)d_in[11];

    launch_all(x, y, state, cell, lstate, ne,
               gate_w, gate_b, update_w, update_b, space_w, space_b,
               (float*)d_out, out_size);
}